// round 3
// baseline (speedup 1.0000x reference)
#include <cuda_runtime.h>
#include <cuda_fp16.h>
#include <math.h>

// Problem dims (fixed)
#define B_      8
#define H_      32
#define TQ_     8
#define KV_     4096
#define D_      128

// Split-KV config
#define NSPLIT_ 8
#define KVS_    (KV_ / NSPLIT_)   // 512 rows per split
#define TS_     32                // KV rows per tile
#define NTILES_ (KVS_ / TS_)      // 16
#define NPART_  (B_ * H_ * NSPLIT_) // 2048

// Scratch for split partials (device globals: allocation-free)
__device__ float g_po[NPART_ * TQ_ * D_];  // unnormalized partial outputs
__device__ float g_pm[NPART_ * TQ_];       // running max per (part, query)
__device__ float g_pl[NPART_ * TQ_];       // running sum-exp per (part, query)

__device__ __forceinline__ float tern(float x, float th) {
    // ternary {-1,0,+1}: strictly outside [-th, th]
    return (fabsf(x) > th) ? copysignf(1.0f, x) : 0.0f;
}

__global__ __launch_bounds__(256, 2)
void attn_split_kernel(const float* __restrict__ q,
                       const float* __restrict__ k,
                       const float* __restrict__ v,
                       const float* __restrict__ logth)
{
    __shared__ __align__(16) float q_sm[TQ_ * D_];   // q * (scale*thresh)
    __shared__ __align__(16) float s_sm[TQ_ * TS_];  // tile scores
    __shared__ __align__(16) float p_sm[TQ_ * TS_];  // tile probs (unnormalized)
    __shared__ __align__(16) float red_sm[8][D_];    // epilogue cross-warp reduce
    __shared__ float alpha_sm[TQ_];                   // per-query rescale

    const int bid   = blockIdx.x;
    const int bh    = bid >> 3;              // (b*H + h)
    const int split = bid & (NSPLIT_ - 1);
    const int h     = bh & (H_ - 1);
    const int t     = threadIdx.x;
    const int w     = t >> 5;                // warp id = query id in phase A2
    const int lane  = t & 31;
    const int ar    = t >> 3;                // phase A: row within tile (0..31)
    const int adq   = t & 7;                 // phase A: d-octant (0..7)

    // softplus (numerically stable, matches jax.nn.softplus)
    const float lt = logth[h];
    const float th = fmaxf(lt, 0.0f) + log1pf(expf(-fabsf(lt)));
    const float qmul = th * 0.08838834764831845f;   // thresh / sqrt(128)

    const float* qb = q + (size_t)bh * (TQ_ * D_);
    const float* kb = k + (size_t)bh * (KV_ * D_) + (size_t)split * (KVS_ * D_);
    const float* vb = v + (size_t)bh * (KV_ * D_) + (size_t)split * (KVS_ * D_);

    // load q scaled by thresh*scale (so k dequant is just {-1,0,1})
    for (int i = t; i < TQ_ * D_; i += 256) q_sm[i] = qb[i] * qmul;
    __syncthreads();

    // output accumulators: thread owns PARTIAL out[j][bd..bd+3] over its rows
    float o0[TQ_], o1[TQ_], o2[TQ_], o3[TQ_];
#pragma unroll
    for (int j = 0; j < TQ_; j++) { o0[j]=0.f; o1[j]=0.f; o2[j]=0.f; o3[j]=0.f; }
    float m_run = -INFINITY, l_run = 0.0f;

    // phase-A thread slice: d-chunks (i*8 + adq) for i=0..3  -> d = i*32 + adq*4
    float4 kk[4];
    {
        const float* kp = kb + ar * D_ + adq * 4;
#pragma unroll
        for (int i = 0; i < 4; i++) kk[i] = *(const float4*)(kp + i * 32);
    }

    const int brow = w << 2;        // phase B: rows w*4..w*4+3 within tile
    const int bd   = lane << 2;     // phase B: output column base

#pragma unroll 1
    for (int tile = 0; tile < NTILES_; tile++) {
        // ---- prefetch V for this tile (used in phase B) ----
        float4 vv[4];
        {
            const float* vp = vb + (size_t)(tile * TS_ + brow) * D_ + bd;
#pragma unroll
            for (int i2 = 0; i2 < 4; i2++) vv[i2] = *(const float4*)(vp + i2 * D_);
        }

        // ---- phase A: partial dot products (ternary dequant folded to q) ----
        float s[TQ_];
#pragma unroll
        for (int j = 0; j < TQ_; j++) s[j] = 0.0f;
#pragma unroll
        for (int i = 0; i < 4; i++) {
            const float4 kq = kk[i];
            const float e0 = tern(kq.x, th);
            const float e1 = tern(kq.y, th);
            const float e2 = tern(kq.z, th);
            const float e3 = tern(kq.w, th);
            const float* qp = q_sm + i * 32 + adq * 4;
#pragma unroll
            for (int j = 0; j < TQ_; j++) {
                const float4 q4 = *(const float4*)(qp + j * D_);
                float acc = s[j];
                acc = fmaf(q4.x, e0, acc);
                acc = fmaf(q4.y, e1, acc);
                acc = fmaf(q4.z, e2, acc);
                acc = fmaf(q4.w, e3, acc);
                s[j] = acc;
            }
        }

        // ---- prefetch next tile's K (kk dead now; hides DRAM latency) ----
        if (tile + 1 < NTILES_) {
            const float* kp = kb + (size_t)((tile + 1) * TS_ + ar) * D_ + adq * 4;
#pragma unroll
            for (int i = 0; i < 4; i++) kk[i] = *(const float4*)(kp + i * 32);
        }

        // ---- reduce partial dots across the 8 d-octant lanes ----
#pragma unroll
        for (int j = 0; j < TQ_; j++) {
            s[j] += __shfl_xor_sync(0xffffffffu, s[j], 1);
            s[j] += __shfl_xor_sync(0xffffffffu, s[j], 2);
            s[j] += __shfl_xor_sync(0xffffffffu, s[j], 4);
        }
        if (adq == 0) {
#pragma unroll
            for (int j = 0; j < TQ_; j++) s_sm[j * TS_ + ar] = s[j];
        }
        __syncthreads();

        // ---- phase A2: online softmax update, warp w owns query w ----
        {
            const float x = s_sm[w * TS_ + lane];
            float mt = x;
#pragma unroll
            for (int off = 16; off > 0; off >>= 1)
                mt = fmaxf(mt, __shfl_xor_sync(0xffffffffu, mt, off));
            const float m_new = fmaxf(m_run, mt);
            const float alpha = __expf(m_run - m_new);  // 0 on first tile (-inf)
            const float p = __expf(x - m_new);
            float ps = p;
#pragma unroll
            for (int off = 16; off > 0; off >>= 1)
                ps += __shfl_xor_sync(0xffffffffu, ps, off);
            l_run = l_run * alpha + ps;
            m_run = m_new;
            p_sm[w * TS_ + lane] = p;
            if (lane == 0) alpha_sm[w] = alpha;
        }
        __syncthreads();

        // ---- phase B: rescale + accumulate P·V over THIS WARP'S 4 rows ----
        // (partials are summed across warps in the epilogue; rescaling is
        //  linear so per-warp partials rescaled identically stay consistent)
#pragma unroll
        for (int i2 = 0; i2 < 4; i2++) {
            vv[i2].x = __half2float(__float2half_rn(vv[i2].x));
            vv[i2].y = __half2float(__float2half_rn(vv[i2].y));
            vv[i2].z = __half2float(__float2half_rn(vv[i2].z));
            vv[i2].w = __half2float(__float2half_rn(vv[i2].w));
        }
#pragma unroll
        for (int j = 0; j < TQ_; j++) {
            const float a = alpha_sm[j];
            const float4 p4 = *(const float4*)&p_sm[j * TS_ + brow];
            float x0 = o0[j] * a, x1 = o1[j] * a, x2 = o2[j] * a, x3 = o3[j] * a;
            x0 = fmaf(p4.x, vv[0].x, x0); x1 = fmaf(p4.x, vv[0].y, x1);
            x2 = fmaf(p4.x, vv[0].z, x2); x3 = fmaf(p4.x, vv[0].w, x3);
            x0 = fmaf(p4.y, vv[1].x, x0); x1 = fmaf(p4.y, vv[1].y, x1);
            x2 = fmaf(p4.y, vv[1].z, x2); x3 = fmaf(p4.y, vv[1].w, x3);
            x0 = fmaf(p4.z, vv[2].x, x0); x1 = fmaf(p4.z, vv[2].y, x1);
            x2 = fmaf(p4.z, vv[2].z, x2); x3 = fmaf(p4.z, vv[2].w, x3);
            x0 = fmaf(p4.w, vv[3].x, x0); x1 = fmaf(p4.w, vv[3].y, x1);
            x2 = fmaf(p4.w, vv[3].z, x2); x3 = fmaf(p4.w, vv[3].w, x3);
            o0[j] = x0; o1[j] = x1; o2[j] = x2; o3[j] = x3;
        }
    }

    // ---- epilogue: reduce per-warp partials across the 8 warps, write ----
    {
        const size_t pbase = (size_t)bid * (TQ_ * D_);
#pragma unroll 1
        for (int j = 0; j < TQ_; j++) {
            __syncthreads();   // previous iteration's reads done
            *(float4*)&red_sm[w][bd] = make_float4(o0[j], o1[j], o2[j], o3[j]);
            __syncthreads();
            if (t < D_) {
                float acc = red_sm[0][t];
#pragma unroll
                for (int w2 = 1; w2 < 8; w2++) acc += red_sm[w2][t];
                g_po[pbase + j * D_ + t] = acc;
            }
        }
        if (lane == 0) {
            g_pm[bid * TQ_ + w] = m_run;
            g_pl[bid * TQ_ + w] = l_run;
        }
    }
}

__global__ __launch_bounds__(256)
void combine_kernel(float* __restrict__ out)
{
    const int bh = blockIdx.x;          // 0..255
    const int t  = threadIdx.x;
    const int j  = t >> 5;              // query
    const int d4 = (t & 31) << 2;       // column base

    float m[NSPLIT_];
    float M = -INFINITY;
#pragma unroll
    for (int i = 0; i < NSPLIT_; i++) {
        m[i] = g_pm[(bh * NSPLIT_ + i) * TQ_ + j];
        M = fmaxf(M, m[i]);
    }
    float W = 0.0f;
    float ax = 0.f, ay = 0.f, az = 0.f, aw = 0.f;
#pragma unroll
    for (int i = 0; i < NSPLIT_; i++) {
        const float wgt = __expf(m[i] - M);
        W = fmaf(wgt, g_pl[(bh * NSPLIT_ + i) * TQ_ + j], W);
        const float4 oi = *(const float4*)&g_po[((size_t)(bh * NSPLIT_ + i) * TQ_ + j) * D_ + d4];
        ax = fmaf(wgt, oi.x, ax);
        ay = fmaf(wgt, oi.y, ay);
        az = fmaf(wgt, oi.z, az);
        aw = fmaf(wgt, oi.w, aw);
    }
    const float inv = 1.0f / W;
    float4 r = make_float4(ax * inv, ay * inv, az * inv, aw * inv);
    *(float4*)&out[(size_t)bh * (TQ_ * D_) + j * D_ + d4] = r;
}

extern "C" void kernel_launch(void* const* d_in, const int* in_sizes, int n_in,
                              void* d_out, int out_size)
{
    const float* q    = (const float*)d_in[0];
    const float* k    = (const float*)d_in[1];
    const float* v    = (const float*)d_in[2];
    const float* logt = (const float*)d_in[3];
    float* out = (float*)d_out;

    attn_split_kernel<<<NPART_, 256>>>(q, k, v, logt);
    combine_kernel<<<B_ * H_, 256>>>(out);
}

// round 5
// speedup vs baseline: 1.1282x; 1.1282x over previous
#include <cuda_runtime.h>
#include <cuda_fp16.h>
#include <math.h>

// Problem dims (fixed)
#define B_      8
#define H_      32
#define TQ_     8
#define KV_     4096
#define D_      128

// Split-KV config
#define NSPLIT_ 8
#define KVS_    (KV_ / NSPLIT_)   // 512 rows per split
#define TS_     32                // KV rows per tile
#define NTILES_ (KVS_ / TS_)      // 16
#define NPART_  (B_ * H_ * NSPLIT_) // 2048

typedef unsigned long long u64;

// Scratch for split partials (device globals: allocation-free)
__device__ float g_po[NPART_ * TQ_ * D_];  // unnormalized partial outputs
__device__ float g_pm[NPART_ * TQ_];       // running max per (part, query)
__device__ float g_pl[NPART_ * TQ_];       // running sum-exp per (part, query)

// ---- packed f32x2 helpers (Blackwell) ----
__device__ __forceinline__ u64 fma2(u64 a, u64 b, u64 c) {
    u64 d; asm("fma.rn.f32x2 %0, %1, %2, %3;" : "=l"(d) : "l"(a), "l"(b), "l"(c));
    return d;
}
__device__ __forceinline__ u64 mul2(u64 a, u64 b) {
    u64 d; asm("mul.rn.f32x2 %0, %1, %2;" : "=l"(d) : "l"(a), "l"(b));
    return d;
}
__device__ __forceinline__ u64 pack2(float lo, float hi) {
    u64 d; asm("mov.b64 %0, {%1, %2};" : "=l"(d) : "f"(lo), "f"(hi));
    return d;
}
__device__ __forceinline__ float2 unpack2(u64 a) {
    float lo, hi; asm("mov.b64 {%0, %1}, %2;" : "=f"(lo), "=f"(hi) : "l"(a));
    return make_float2(lo, hi);
}
// fp16 round-trip of two floats, result packed as f32x2
__device__ __forceinline__ u64 h16rt2(float a, float b) {
    __half2 h = __floats2half2_rn(a, b);
    float2 f = __half22float2(h);
    return pack2(f.x, f.y);
}

__device__ __forceinline__ float tern(float x, float th) {
    // ternary {-1,0,+1}: strictly outside [-th, th]
    return (fabsf(x) > th) ? copysignf(1.0f, x) : 0.0f;
}

__global__ __launch_bounds__(256, 2)
void attn_split_kernel(const float* __restrict__ q,
                       const float* __restrict__ k,
                       const float* __restrict__ v,
                       const float* __restrict__ logth)
{
    __shared__ __align__(16) float q_sm[TQ_ * D_];   // q * (scale*thresh)
    __shared__ __align__(16) float s_sm[TQ_ * TS_];  // tile scores
    __shared__ __align__(16) float p_sm[TQ_ * TS_];  // tile probs (unnormalized)
    __shared__ __align__(16) float red_sm[8][D_];    // epilogue cross-warp reduce
    __shared__ float alpha_sm[TQ_];                   // per-query rescale

    const int bid   = blockIdx.x;
    const int bh    = bid >> 3;              // (b*H + h)
    const int split = bid & (NSPLIT_ - 1);
    const int h     = bh & (H_ - 1);
    const int t     = threadIdx.x;
    const int w     = t >> 5;                // warp id = query id in phase A2
    const int lane  = t & 31;
    const int ar    = t >> 3;                // phase A: row within tile (0..31)
    const int adq   = t & 7;                 // phase A: d-octant (0..7)

    // softplus (numerically stable, matches jax.nn.softplus)
    const float lt = logth[h];
    const float th = fmaxf(lt, 0.0f) + log1pf(expf(-fabsf(lt)));
    const float qmul = th * 0.08838834764831845f;   // thresh / sqrt(128)

    const float* qb = q + (size_t)bh * (TQ_ * D_);
    const float* kb = k + (size_t)bh * (KV_ * D_) + (size_t)split * (KVS_ * D_);
    const float* vb = v + (size_t)bh * (KV_ * D_) + (size_t)split * (KVS_ * D_);

    // load q scaled by thresh*scale (so k dequant is just {-1,0,1})
    for (int i = t; i < TQ_ * D_; i += 256) q_sm[i] = qb[i] * qmul;
    __syncthreads();

    // packed output accumulators: o01 = cols (bd,bd+1), o23 = cols (bd+2,bd+3)
    u64 o01[TQ_], o23[TQ_];
#pragma unroll
    for (int j = 0; j < TQ_; j++) { o01[j] = 0ULL; o23[j] = 0ULL; }
    float m_run = -INFINITY, l_run = 0.0f;

    // phase-A thread slice: d-chunks (i*8 + adq) for i=0..3  -> d = i*32 + adq*4
    float4 kk[4];
    {
        const float* kp = kb + ar * D_ + adq * 4;
#pragma unroll
        for (int i = 0; i < 4; i++) kk[i] = *(const float4*)(kp + i * 32);
    }

    const int brow = w << 2;        // phase B: rows w*4..w*4+3 within tile
    const int bd   = lane << 2;     // phase B: output column base

#pragma unroll 1
    for (int tile = 0; tile < NTILES_; tile++) {
        // ---- prefetch V for this tile (used in phase B) ----
        float4 vv[4];
        {
            const float* vp = vb + (size_t)(tile * TS_ + brow) * D_ + bd;
#pragma unroll
            for (int i2 = 0; i2 < 4; i2++) vv[i2] = *(const float4*)(vp + i2 * D_);
        }

        // ---- phase A: packed partial dots (ternary dequant folded to q) ----
        u64 s2[TQ_];
#pragma unroll
        for (int j = 0; j < TQ_; j++) s2[j] = 0ULL;
#pragma unroll
        for (int i = 0; i < 4; i++) {
            const float4 kq = kk[i];
            const u64 E01 = pack2(tern(kq.x, th), tern(kq.y, th));
            const u64 E23 = pack2(tern(kq.z, th), tern(kq.w, th));
            const float* qp = q_sm + i * 32 + adq * 4;
#pragma unroll
            for (int j = 0; j < TQ_; j++) {
                // ld.shared.v2.b64: two pre-packed f32 pairs, zero pack cost
                const ulonglong2 q2 = *(const ulonglong2*)(qp + j * D_);
                u64 acc = s2[j];
                acc = fma2(q2.x, E01, acc);
                acc = fma2(q2.y, E23, acc);
                s2[j] = acc;
            }
        }

        // ---- prefetch next tile's K (kk dead now; hides DRAM latency) ----
        if (tile + 1 < NTILES_) {
            const float* kp = kb + (size_t)((tile + 1) * TS_ + ar) * D_ + adq * 4;
#pragma unroll
            for (int i = 0; i < 4; i++) kk[i] = *(const float4*)(kp + i * 32);
        }

        // ---- reduce packed halves + across the 8 d-octant lanes ----
        float s[TQ_];
#pragma unroll
        for (int j = 0; j < TQ_; j++) {
            const float2 sp = unpack2(s2[j]);
            float sv = sp.x + sp.y;
            sv += __shfl_xor_sync(0xffffffffu, sv, 1);
            sv += __shfl_xor_sync(0xffffffffu, sv, 2);
            sv += __shfl_xor_sync(0xffffffffu, sv, 4);
            s[j] = sv;
        }
        if (adq == 0) {
#pragma unroll
            for (int j = 0; j < TQ_; j++) s_sm[j * TS_ + ar] = s[j];
        }
        __syncthreads();

        // ---- phase A2: online softmax update, warp w owns query w ----
        {
            const float x = s_sm[w * TS_ + lane];
            float mt = x;
#pragma unroll
            for (int off = 16; off > 0; off >>= 1)
                mt = fmaxf(mt, __shfl_xor_sync(0xffffffffu, mt, off));
            const float m_new = fmaxf(m_run, mt);
            const float alpha = __expf(m_run - m_new);  // 0 on first tile (-inf)
            const float p = __expf(x - m_new);
            float ps = p;
#pragma unroll
            for (int off = 16; off > 0; off >>= 1)
                ps += __shfl_xor_sync(0xffffffffu, ps, off);
            l_run = l_run * alpha + ps;
            m_run = m_new;
            p_sm[w * TS_ + lane] = p;
            if (lane == 0) alpha_sm[w] = alpha;
        }
        __syncthreads();

        // ---- phase B: packed rescale + P·V over THIS WARP'S 4 rows ----
        u64 V01[4], V23[4];
#pragma unroll
        for (int i2 = 0; i2 < 4; i2++) {
            V01[i2] = h16rt2(vv[i2].x, vv[i2].y);   // exact fp16 round-trip
            V23[i2] = h16rt2(vv[i2].z, vv[i2].w);
        }
#pragma unroll
        for (int j = 0; j < TQ_; j++) {
            const float a = alpha_sm[j];
            const u64 A2 = pack2(a, a);
            const float4 p4 = *(const float4*)&p_sm[j * TS_ + brow];
            u64 x01 = mul2(o01[j], A2);
            u64 x23 = mul2(o23[j], A2);
            u64 P;
            P = pack2(p4.x, p4.x); x01 = fma2(P, V01[0], x01); x23 = fma2(P, V23[0], x23);
            P = pack2(p4.y, p4.y); x01 = fma2(P, V01[1], x01); x23 = fma2(P, V23[1], x23);
            P = pack2(p4.z, p4.z); x01 = fma2(P, V01[2], x01); x23 = fma2(P, V23[2], x23);
            P = pack2(p4.w, p4.w); x01 = fma2(P, V01[3], x01); x23 = fma2(P, V23[3], x23);
            o01[j] = x01; o23[j] = x23;
        }
    }

    // ---- epilogue: reduce per-warp partials across the 8 warps, write ----
    {
        const size_t pbase = (size_t)bid * (TQ_ * D_);
#pragma unroll 1
        for (int j = 0; j < TQ_; j++) {
            __syncthreads();   // previous iteration's reads done
            const float2 a01 = unpack2(o01[j]);
            const float2 a23 = unpack2(o23[j]);
            *(float4*)&red_sm[w][bd] = make_float4(a01.x, a01.y, a23.x, a23.y);
            __syncthreads();
            if (t < D_) {
                float acc = red_sm[0][t];
#pragma unroll
                for (int w2 = 1; w2 < 8; w2++) acc += red_sm[w2][t];
                g_po[pbase + j * D_ + t] = acc;
            }
        }
        if (lane == 0) {
            g_pm[bid * TQ_ + w] = m_run;
            g_pl[bid * TQ_ + w] = l_run;
        }
    }
}

__global__ __launch_bounds__(256)
void combine_kernel(float* __restrict__ out)
{
    const int bh = blockIdx.x;          // 0..255
    const int t  = threadIdx.x;
    const int j  = t >> 5;              // query
    const int d4 = (t & 31) << 2;       // column base

    float m[NSPLIT_];
    float M = -INFINITY;
#pragma unroll
    for (int i = 0; i < NSPLIT_; i++) {
        m[i] = g_pm[(bh * NSPLIT_ + i) * TQ_ + j];
        M = fmaxf(M, m[i]);
    }
    float W = 0.0f;
    float ax = 0.f, ay = 0.f, az = 0.f, aw = 0.f;
#pragma unroll
    for (int i = 0; i < NSPLIT_; i++) {
        const float wgt = __expf(m[i] - M);
        W = fmaf(wgt, g_pl[(bh * NSPLIT_ + i) * TQ_ + j], W);
        const float4 oi = *(const float4*)&g_po[((size_t)(bh * NSPLIT_ + i) * TQ_ + j) * D_ + d4];
        ax = fmaf(wgt, oi.x, ax);
        ay = fmaf(wgt, oi.y, ay);
        az = fmaf(wgt, oi.z, az);
        aw = fmaf(wgt, oi.w, aw);
    }
    const float inv = 1.0f / W;
    float4 r = make_float4(ax * inv, ay * inv, az * inv, aw * inv);
    *(float4*)&out[(size_t)bh * (TQ_ * D_) + j * D_ + d4] = r;
}

extern "C" void kernel_launch(void* const* d_in, const int* in_sizes, int n_in,
                              void* d_out, int out_size)
{
    const float* q    = (const float*)d_in[0];
    const float* k    = (const float*)d_in[1];
    const float* v    = (const float*)d_in[2];
    const float* logt = (const float*)d_in[3];
    float* out = (float*)d_out;

    attn_split_kernel<<<NPART_, 256>>>(q, k, v, logt);
    combine_kernel<<<B_ * H_, 256>>>(out);
}

// round 6
// speedup vs baseline: 1.1527x; 1.0217x over previous
#include <cuda_runtime.h>
#include <cuda_fp16.h>
#include <math.h>

// Problem dims (fixed)
#define B_      8
#define H_      32
#define TQ_     8
#define KV_     4096
#define D_      128

// Split-KV config
#define NSPLIT_ 8
#define KVS_    (KV_ / NSPLIT_)   // 512 rows per split
#define TS_     32                // KV rows per tile
#define NTILES_ (KVS_ / TS_)      // 16
#define NPART_  (B_ * H_ * NSPLIT_) // 2048

typedef unsigned long long u64;

// Scratch for split partials (device globals: allocation-free)
__device__ float g_po[NPART_ * TQ_ * D_];  // unnormalized partial outputs
__device__ float g_pm[NPART_ * TQ_];       // running max per (part, query)
__device__ float g_pl[NPART_ * TQ_];       // running sum-exp per (part, query)

// ---- packed f32x2 helpers (Blackwell) ----
__device__ __forceinline__ u64 fma2(u64 a, u64 b, u64 c) {
    u64 d; asm("fma.rn.f32x2 %0, %1, %2, %3;" : "=l"(d) : "l"(a), "l"(b), "l"(c));
    return d;
}
__device__ __forceinline__ u64 mul2(u64 a, u64 b) {
    u64 d; asm("mul.rn.f32x2 %0, %1, %2;" : "=l"(d) : "l"(a), "l"(b));
    return d;
}
__device__ __forceinline__ u64 pack2(float lo, float hi) {
    u64 d; asm("mov.b64 %0, {%1, %2};" : "=l"(d) : "f"(lo), "f"(hi));
    return d;
}
__device__ __forceinline__ float2 unpack2(u64 a) {
    float lo, hi; asm("mov.b64 {%0, %1}, %2;" : "=f"(lo), "=f"(hi) : "l"(a));
    return make_float2(lo, hi);
}
// fp16 round-trip of two floats, result packed as f32x2
__device__ __forceinline__ u64 h16rt2(float a, float b) {
    __half2 h = __floats2half2_rn(a, b);
    float2 f = __half22float2(h);
    return pack2(f.x, f.y);
}

__device__ __forceinline__ float tern(float x, float th) {
    // ternary {-1,0,+1}: strictly outside [-th, th]
    return (fabsf(x) > th) ? copysignf(1.0f, x) : 0.0f;
}

__global__ __launch_bounds__(256, 2)
void attn_split_kernel(const float* __restrict__ q,
                       const float* __restrict__ k,
                       const float* __restrict__ v,
                       const float* __restrict__ logth)
{
    __shared__ __align__(16) float q_sm[TQ_ * D_];    // q * (scale*thresh)
    __shared__ __align__(16) float p_w[8][TQ_][4];    // warp-private probs [w][j][rr]
    __shared__ float alpha_w[8][TQ_];                 // warp-private rescale
    __shared__ float m_sm[8][TQ_];                    // epilogue: per-warp m
    __shared__ float l_sm[8][TQ_];                    // epilogue: per-warp l
    __shared__ __align__(16) float red_sm[8][D_];     // epilogue cross-warp reduce

    const int bid   = blockIdx.x;
    const int bh    = bid >> 3;              // (b*H + h)
    const int split = bid & (NSPLIT_ - 1);
    const int h     = bh & (H_ - 1);
    const int t     = threadIdx.x;
    const int w     = t >> 5;                // warp id
    const int lane  = t & 31;
    const int ar    = t >> 3;                // dot row within tile (0..31): 4w + rr
    const int adq   = t & 7;                 // d-octant AND assigned query
    const int rr    = lane >> 3;             // row-within-warp (0..3)

    // softplus (numerically stable, matches jax.nn.softplus)
    const float lt = logth[h];
    const float th = fmaxf(lt, 0.0f) + log1pf(expf(-fabsf(lt)));
    const float qmul = th * 0.08838834764831845f;   // thresh / sqrt(128)

    const float* qb = q + (size_t)bh * (TQ_ * D_);
    const float* kb = k + (size_t)bh * (KV_ * D_) + (size_t)split * (KVS_ * D_);
    const float* vb = v + (size_t)bh * (KV_ * D_) + (size_t)split * (KVS_ * D_);

    // load q scaled by thresh*scale (so k dequant is just {-1,0,1})
    for (int i = t; i < TQ_ * D_; i += 256) q_sm[i] = qb[i] * qmul;
    __syncthreads();

    // packed output accumulators (this warp's rows only; merged in epilogue)
    u64 o01[TQ_], o23[TQ_];
#pragma unroll
    for (int j = 0; j < TQ_; j++) { o01[j] = 0ULL; o23[j] = 0ULL; }
    // per-warp online softmax state for ASSIGNED query (adq), replicated in rr
    float m_run = -INFINITY, l_run = 0.0f;

    // dot-phase thread slice: d-chunks (i*8 + adq) -> d = i*32 + adq*4
    float4 kk[4];
    {
        const float* kp = kb + ar * D_ + adq * 4;
#pragma unroll
        for (int i = 0; i < 4; i++) kk[i] = *(const float4*)(kp + i * 32);
    }

    const int brow = w << 2;        // this warp's rows: 4w..4w+3 (== its ar range)
    const int bd   = lane << 2;     // output column base

#pragma unroll 1
    for (int tile = 0; tile < NTILES_; tile++) {
        // ---- prefetch V for this tile (this warp's 4 rows) ----
        float4 vv[4];
        {
            const float* vp = vb + (size_t)(tile * TS_ + brow) * D_ + bd;
#pragma unroll
            for (int i2 = 0; i2 < 4; i2++) vv[i2] = *(const float4*)(vp + i2 * D_);
        }

        // ---- phase A: packed partial dots (ternary dequant folded to q) ----
        u64 s2[TQ_];
#pragma unroll
        for (int j = 0; j < TQ_; j++) s2[j] = 0ULL;
#pragma unroll
        for (int i = 0; i < 4; i++) {
            const float4 kq = kk[i];
            const u64 E01 = pack2(tern(kq.x, th), tern(kq.y, th));
            const u64 E23 = pack2(tern(kq.z, th), tern(kq.w, th));
            const float* qp = q_sm + i * 32 + adq * 4;
#pragma unroll
            for (int j = 0; j < TQ_; j++) {
                const ulonglong2 q2 = *(const ulonglong2*)(qp + j * D_);
                u64 acc = s2[j];
                acc = fma2(q2.x, E01, acc);
                acc = fma2(q2.y, E23, acc);
                s2[j] = acc;
            }
        }

        // ---- prefetch next tile's K (kk dead now; hides DRAM latency) ----
        if (tile + 1 < NTILES_) {
            const float* kp = kb + (size_t)((tile + 1) * TS_ + ar) * D_ + adq * 4;
#pragma unroll
            for (int i = 0; i < 4; i++) kk[i] = *(const float4*)(kp + i * 32);
        }

        // ---- reduce packed halves + across the 8 d-octant lanes ----
        float s[TQ_];
#pragma unroll
        for (int j = 0; j < TQ_; j++) {
            const float2 sp = unpack2(s2[j]);
            float sv = sp.x + sp.y;
            sv += __shfl_xor_sync(0xffffffffu, sv, 1);
            sv += __shfl_xor_sync(0xffffffffu, sv, 2);
            sv += __shfl_xor_sync(0xffffffffu, sv, 4);
            s[j] = sv;   // all lanes of row-group ar now hold s[j] for this row
        }

        // ---- per-warp online softmax over its 4 rows, query adq per lane ----
        {
            // dynamic select s[adq] via 7-SEL tree
            const bool b0 = (adq & 1), b1 = (adq & 2), b2 = (adq & 4);
            const float a0 = b0 ? s[1] : s[0];
            const float a1 = b0 ? s[3] : s[2];
            const float a2 = b0 ? s[5] : s[4];
            const float a3 = b0 ? s[7] : s[6];
            const float c0 = b1 ? a1 : a0;
            const float c1 = b1 ? a3 : a2;
            const float own = b2 ? c1 : c0;   // score(row=ar, query=adq)

            float mt = own;
            mt = fmaxf(mt, __shfl_xor_sync(0xffffffffu, mt, 8));
            mt = fmaxf(mt, __shfl_xor_sync(0xffffffffu, mt, 16));
            const float m_new = fmaxf(m_run, mt);
            const float alpha = __expf(m_run - m_new);  // 0 on first tile
            const float p = __expf(own - m_new);
            float ps = p;
            ps += __shfl_xor_sync(0xffffffffu, ps, 8);
            ps += __shfl_xor_sync(0xffffffffu, ps, 16);
            l_run = l_run * alpha + ps;
            m_run = m_new;

            p_w[w][adq][rr] = p;
            if (rr == 0) alpha_w[w][adq] = alpha;
        }
        __syncwarp();

        // ---- phase B: packed rescale + P·V over this warp's 4 rows ----
        u64 V01[4], V23[4];
#pragma unroll
        for (int i2 = 0; i2 < 4; i2++) {
            V01[i2] = h16rt2(vv[i2].x, vv[i2].y);   // exact fp16 round-trip
            V23[i2] = h16rt2(vv[i2].z, vv[i2].w);
        }
#pragma unroll
        for (int j = 0; j < TQ_; j++) {
            const float a = alpha_w[w][j];
            const u64 A2 = pack2(a, a);
            const float4 p4 = *(const float4*)&p_w[w][j][0];
            u64 x01 = mul2(o01[j], A2);
            u64 x23 = mul2(o23[j], A2);
            u64 P;
            P = pack2(p4.x, p4.x); x01 = fma2(P, V01[0], x01); x23 = fma2(P, V23[0], x23);
            P = pack2(p4.y, p4.y); x01 = fma2(P, V01[1], x01); x23 = fma2(P, V23[1], x23);
            P = pack2(p4.z, p4.z); x01 = fma2(P, V01[2], x01); x23 = fma2(P, V23[2], x23);
            P = pack2(p4.w, p4.w); x01 = fma2(P, V01[3], x01); x23 = fma2(P, V23[3], x23);
            o01[j] = x01; o23[j] = x23;
        }
        __syncwarp();   // protect p_w/alpha_w before next tile's overwrite
    }

    // ---- epilogue: merge 8 per-warp (m,l,O) by log-sum-exp, write partial ----
    if (rr == 0) { m_sm[w][adq] = m_run; l_sm[w][adq] = l_run; }
    __syncthreads();

    float sc[TQ_];
#pragma unroll
    for (int j = 0; j < TQ_; j++) {
        float M = m_sm[0][j];
#pragma unroll
        for (int w2 = 1; w2 < 8; w2++) M = fmaxf(M, m_sm[w2][j]);
        sc[j] = __expf(m_sm[w][j] - M);   // this warp's rescale to CTA max
    }
    {
        const size_t pbase = (size_t)bid * (TQ_ * D_);
#pragma unroll 1
        for (int j = 0; j < TQ_; j++) {
            __syncthreads();   // previous iteration's reads done
            const u64 S2 = pack2(sc[j], sc[j]);
            const float2 a01 = unpack2(mul2(o01[j], S2));
            const float2 a23 = unpack2(mul2(o23[j], S2));
            *(float4*)&red_sm[w][bd] = make_float4(a01.x, a01.y, a23.x, a23.y);
            __syncthreads();
            if (t < D_) {
                float acc = red_sm[0][t];
#pragma unroll
                for (int w2 = 1; w2 < 8; w2++) acc += red_sm[w2][t];
                g_po[pbase + j * D_ + t] = acc;
            }
        }
        if (t < TQ_) {   // thread t == query j
            float M = m_sm[0][t];
#pragma unroll
            for (int w2 = 1; w2 < 8; w2++) M = fmaxf(M, m_sm[w2][t]);
            float L = 0.0f;
#pragma unroll
            for (int w2 = 0; w2 < 8; w2++)
                L = fmaf(__expf(m_sm[w2][t] - M), l_sm[w2][t], L);
            g_pm[bid * TQ_ + t] = M;
            g_pl[bid * TQ_ + t] = L;
        }
    }
}

__global__ __launch_bounds__(256)
void combine_kernel(float* __restrict__ out)
{
    const int bh = blockIdx.x;          // 0..255
    const int t  = threadIdx.x;
    const int j  = t >> 5;              // query
    const int d4 = (t & 31) << 2;       // column base

    float m[NSPLIT_];
    float M = -INFINITY;
#pragma unroll
    for (int i = 0; i < NSPLIT_; i++) {
        m[i] = g_pm[(bh * NSPLIT_ + i) * TQ_ + j];
        M = fmaxf(M, m[i]);
    }
    float W = 0.0f;
    float ax = 0.f, ay = 0.f, az = 0.f, aw = 0.f;
#pragma unroll
    for (int i = 0; i < NSPLIT_; i++) {
        const float wgt = __expf(m[i] - M);
        W = fmaf(wgt, g_pl[(bh * NSPLIT_ + i) * TQ_ + j], W);
        const float4 oi = *(const float4*)&g_po[((size_t)(bh * NSPLIT_ + i) * TQ_ + j) * D_ + d4];
        ax = fmaf(wgt, oi.x, ax);
        ay = fmaf(wgt, oi.y, ay);
        az = fmaf(wgt, oi.z, az);
        aw = fmaf(wgt, oi.w, aw);
    }
    const float inv = 1.0f / W;
    float4 r = make_float4(ax * inv, ay * inv, az * inv, aw * inv);
    *(float4*)&out[(size_t)bh * (TQ_ * D_) + j * D_ + d4] = r;
}

// diagnostic: pads launch count so ncu (-s 5 -c 1) captures attn_split_kernel
__global__ void nop_kernel() {}

extern "C" void kernel_launch(void* const* d_in, const int* in_sizes, int n_in,
                              void* d_out, int out_size)
{
    const float* q    = (const float*)d_in[0];
    const float* k    = (const float*)d_in[1];
    const float* v    = (const float*)d_in[2];
    const float* logt = (const float*)d_in[3];
    float* out = (float*)d_out;

    attn_split_kernel<<<NPART_, 256>>>(q, k, v, logt);
    combine_kernel<<<B_ * H_, 256>>>(out);
    nop_kernel<<<1, 32>>>();
    nop_kernel<<<1, 32>>>();
    nop_kernel<<<1, 32>>>();
}

// round 8
// speedup vs baseline: 1.2895x; 1.1187x over previous
#include <cuda_runtime.h>
#include <cuda_fp16.h>
#include <math.h>

// Problem dims (fixed)
#define B_      8
#define H_      32
#define TQ_     8
#define KV_     4096
#define D_      128

// Split-KV config
#define NSPLIT_ 8
#define KVS_    (KV_ / NSPLIT_)   // 512 rows per split
#define TS_     32                // KV rows per tile
#define NTILES_ (KVS_ / TS_)      // 16
#define NPART_  (B_ * H_ * NSPLIT_) // 2048

typedef unsigned long long u64;

// Scratch for split partials (device globals: allocation-free)
__device__ float g_po[NPART_ * TQ_ * D_];  // unnormalized partial outputs
__device__ float g_pm[NPART_ * TQ_];       // running max per (part, query)
__device__ float g_pl[NPART_ * TQ_];       // running sum-exp per (part, query)

// ---- packed f32x2 helpers (Blackwell) ----
__device__ __forceinline__ u64 fma2(u64 a, u64 b, u64 c) {
    u64 d; asm("fma.rn.f32x2 %0, %1, %2, %3;" : "=l"(d) : "l"(a), "l"(b), "l"(c));
    return d;
}
__device__ __forceinline__ u64 mul2(u64 a, u64 b) {
    u64 d; asm("mul.rn.f32x2 %0, %1, %2;" : "=l"(d) : "l"(a), "l"(b));
    return d;
}
__device__ __forceinline__ u64 pack2(float lo, float hi) {
    u64 d; asm("mov.b64 %0, {%1, %2};" : "=l"(d) : "f"(lo), "f"(hi));
    return d;
}
__device__ __forceinline__ float2 unpack2(u64 a) {
    float lo, hi; asm("mov.b64 {%0, %1}, %2;" : "=f"(lo), "=f"(hi) : "l"(a));
    return make_float2(lo, hi);
}
// fp16 round-trip of two floats, result packed as f32x2
__device__ __forceinline__ u64 h16rt2(float a, float b) {
    __half2 h = __floats2half2_rn(a, b);
    float2 f = __half22float2(h);
    return pack2(f.x, f.y);
}

__device__ __forceinline__ float tern(float x, float th) {
    // ternary {-1,0,+1}: strictly outside [-th, th]
    return (fabsf(x) > th) ? copysignf(1.0f, x) : 0.0f;
}

__global__ __launch_bounds__(256, 2)
void attn_split_kernel(const float* __restrict__ q,
                       const float* __restrict__ k,
                       const float* __restrict__ v,
                       const float* __restrict__ logth)
{
    __shared__ __align__(16) float q_sm[TQ_ * D_];    // q * (scale*thresh)
    __shared__ __align__(16) float p_w[8][TQ_][4];    // warp-private probs [w][j][rr]
    __shared__ float m_sm[8][TQ_];                    // epilogue: per-warp m
    __shared__ float l_sm[8][TQ_];                    // epilogue: per-warp l
    __shared__ __align__(16) float red_sm[8][D_];     // epilogue cross-warp reduce

    const int bid   = blockIdx.x;
    const int bh    = bid >> 3;              // (b*H + h)
    const int split = bid & (NSPLIT_ - 1);
    const int h     = bh & (H_ - 1);
    const int t     = threadIdx.x;
    const int w     = t >> 5;                // warp id
    const int lane  = t & 31;
    const int ar    = t >> 3;                // dot row within tile (0..31): 4w + rr
    const int adq   = t & 7;                 // d-octant AND assigned query
    const int rr    = lane >> 3;             // row-within-warp (0..3)

    // softplus (numerically stable, matches jax.nn.softplus)
    const float lt = logth[h];
    const float th = fmaxf(lt, 0.0f) + log1pf(expf(-fabsf(lt)));
    const float qmul = th * 0.08838834764831845f;   // thresh / sqrt(128)

    const float* qb = q + (size_t)bh * (TQ_ * D_);
    const float* kb = k + (size_t)bh * (KV_ * D_) + (size_t)split * (KVS_ * D_);
    const float* vb = v + (size_t)bh * (KV_ * D_) + (size_t)split * (KVS_ * D_);

    // load q scaled by thresh*scale (so k dequant is just {-1,0,1})
    for (int i = t; i < TQ_ * D_; i += 256) q_sm[i] = qb[i] * qmul;
    __syncthreads();

    // packed output accumulators (this warp's rows only; merged in epilogue)
    u64 o01[TQ_], o23[TQ_];
#pragma unroll
    for (int j = 0; j < TQ_; j++) { o01[j] = 0ULL; o23[j] = 0ULL; }
    // per-warp online softmax state for ASSIGNED query (adq), replicated in rr
    float m_run = -INFINITY, l_run = 0.0f;

    // dot-phase thread slice: d-chunks (i*8 + adq) -> d = i*32 + adq*4
    float4 kk[4];
    {
        const float* kp = kb + ar * D_ + adq * 4;
#pragma unroll
        for (int i = 0; i < 4; i++) kk[i] = *(const float4*)(kp + i * 32);
    }

    const int brow = w << 2;        // this warp's rows: 4w..4w+3 (== its ar range)
    const int bd   = lane << 2;     // output column base

#pragma unroll 1
    for (int tile = 0; tile < NTILES_; tile++) {
        // ---- prefetch V for this tile (this warp's 4 rows) ----
        float4 vv[4];
        {
            const float* vp = vb + (size_t)(tile * TS_ + brow) * D_ + bd;
#pragma unroll
            for (int i2 = 0; i2 < 4; i2++) vv[i2] = *(const float4*)(vp + i2 * D_);
        }

        // ---- phase A: packed partial dots (ternary dequant folded to q) ----
        // s2[j] = packed pair of PARTIAL sums for query j (two d-interleaved halves)
        u64 s2[TQ_];
#pragma unroll
        for (int j = 0; j < TQ_; j++) s2[j] = 0ULL;
#pragma unroll
        for (int i = 0; i < 4; i++) {
            const float4 kq = kk[i];
            const u64 E01 = pack2(tern(kq.x, th), tern(kq.y, th));
            const u64 E23 = pack2(tern(kq.z, th), tern(kq.w, th));
            const float* qp = q_sm + i * 32 + adq * 4;
#pragma unroll
            for (int j = 0; j < TQ_; j++) {
                const ulonglong2 q2 = *(const ulonglong2*)(qp + j * D_);
                u64 acc = s2[j];
                acc = fma2(q2.x, E01, acc);
                acc = fma2(q2.y, E23, acc);
                s2[j] = acc;
            }
        }
        // collapse each query's packed halves to a scalar
        float s[TQ_];
#pragma unroll
        for (int j = 0; j < TQ_; j++) {
            const float2 hp = unpack2(s2[j]);
            s[j] = hp.x + hp.y;
        }

        // ---- prefetch next tile's K (kk dead now; hides DRAM latency) ----
        if (tile + 1 < NTILES_) {
            const float* kp = kb + (size_t)((tile + 1) * TS_ + ar) * D_ + adq * 4;
#pragma unroll
            for (int i = 0; i < 4; i++) kk[i] = *(const float4*)(kp + i * 32);
        }

        // ---- scalar reduce-scatter: 8 query-dots over 8 d-octant lanes ----
        // 3 rounds, payload halves each round; lane adq ends with query adq.
        float own;
        {
            const bool b2 = (adq & 4) != 0;
            const bool b1 = (adq & 2) != 0;
            const bool b0 = (adq & 1) != 0;
            // round 1 (xor 4): keep our quad (base = 4*b2), send the other quad
            const float r0 = __shfl_xor_sync(0xffffffffu, b2 ? s[0] : s[4], 4);
            const float r1 = __shfl_xor_sync(0xffffffffu, b2 ? s[1] : s[5], 4);
            const float r2 = __shfl_xor_sync(0xffffffffu, b2 ? s[2] : s[6], 4);
            const float r3 = __shfl_xor_sync(0xffffffffu, b2 ? s[3] : s[7], 4);
            const float A0 = (b2 ? s[4] : s[0]) + r0;   // query 4*b2 + 0
            const float A1 = (b2 ? s[5] : s[1]) + r1;   // query 4*b2 + 1
            const float A2 = (b2 ? s[6] : s[2]) + r2;   // query 4*b2 + 2
            const float A3 = (b2 ? s[7] : s[3]) + r3;   // query 4*b2 + 3
            // round 2 (xor 2): keep our pair, send the other pair
            const float r4 = __shfl_xor_sync(0xffffffffu, b1 ? A0 : A2, 2);
            const float r5 = __shfl_xor_sync(0xffffffffu, b1 ? A1 : A3, 2);
            const float C0 = (b1 ? A2 : A0) + r4;       // query 4*b2+2*b1 + 0
            const float C1 = (b1 ? A3 : A1) + r5;       // query 4*b2+2*b1 + 1
            // round 3 (xor 1): keep our element
            const float r6 = __shfl_xor_sync(0xffffffffu, b0 ? C0 : C1, 1);
            own = (b0 ? C1 : C0) + r6;                  // score(row=ar, query=adq)
        }

        // ---- per-warp online softmax over its 4 rows, query adq per lane ----
        float alpha;
        {
            float mt = own;
            mt = fmaxf(mt, __shfl_xor_sync(0xffffffffu, mt, 8));
            mt = fmaxf(mt, __shfl_xor_sync(0xffffffffu, mt, 16));
            const float m_new = fmaxf(m_run, mt);
            alpha = __expf(m_run - m_new);  // 0 on first tile
            const float p = __expf(own - m_new);
            float ps = p;
            ps += __shfl_xor_sync(0xffffffffu, ps, 8);
            ps += __shfl_xor_sync(0xffffffffu, ps, 16);
            l_run = l_run * alpha + ps;
            m_run = m_new;
            p_w[w][adq][rr] = p;
        }
        __syncwarp();

        // ---- phase B: packed rescale + P·V over this warp's 4 rows ----
        u64 V01[4], V23[4];
#pragma unroll
        for (int i2 = 0; i2 < 4; i2++) {
            V01[i2] = h16rt2(vv[i2].x, vv[i2].y);   // exact fp16 round-trip
            V23[i2] = h16rt2(vv[i2].z, vv[i2].w);
        }
#pragma unroll
        for (int j = 0; j < TQ_; j++) {
            // alpha for query j lives (replicated) at lane j of each 8-lane group
            const float a = __shfl_sync(0xffffffffu, alpha, j, 8);
            const u64 A2v = pack2(a, a);
            const float4 p4 = *(const float4*)&p_w[w][j][0];
            u64 x01 = mul2(o01[j], A2v);
            u64 x23 = mul2(o23[j], A2v);
            u64 P;
            P = pack2(p4.x, p4.x); x01 = fma2(P, V01[0], x01); x23 = fma2(P, V23[0], x23);
            P = pack2(p4.y, p4.y); x01 = fma2(P, V01[1], x01); x23 = fma2(P, V23[1], x23);
            P = pack2(p4.z, p4.z); x01 = fma2(P, V01[2], x01); x23 = fma2(P, V23[2], x23);
            P = pack2(p4.w, p4.w); x01 = fma2(P, V01[3], x01); x23 = fma2(P, V23[3], x23);
            o01[j] = x01; o23[j] = x23;
        }
        __syncwarp();   // protect p_w before next tile's overwrite
    }

    // ---- epilogue: merge 8 per-warp (m,l,O) by log-sum-exp, write partial ----
    if (rr == 0) { m_sm[w][adq] = m_run; l_sm[w][adq] = l_run; }
    __syncthreads();

    float sc[TQ_];
#pragma unroll
    for (int j = 0; j < TQ_; j++) {
        float M = m_sm[0][j];
#pragma unroll
        for (int w2 = 1; w2 < 8; w2++) M = fmaxf(M, m_sm[w2][j]);
        sc[j] = __expf(m_sm[w][j] - M);   // this warp's rescale to CTA max
    }
    {
        const size_t pbase = (size_t)bid * (TQ_ * D_);
#pragma unroll 1
        for (int j = 0; j < TQ_; j++) {
            __syncthreads();   // previous iteration's reads done
            const u64 S2 = pack2(sc[j], sc[j]);
            const float2 a01 = unpack2(mul2(o01[j], S2));
            const float2 a23 = unpack2(mul2(o23[j], S2));
            *(float4*)&red_sm[w][bd] = make_float4(a01.x, a01.y, a23.x, a23.y);
            __syncthreads();
            if (t < D_) {
                float acc = red_sm[0][t];
#pragma unroll
                for (int w2 = 1; w2 < 8; w2++) acc += red_sm[w2][t];
                g_po[pbase + j * D_ + t] = acc;
            }
        }
        if (t < TQ_) {   // thread t == query j
            float M = m_sm[0][t];
#pragma unroll
            for (int w2 = 1; w2 < 8; w2++) M = fmaxf(M, m_sm[w2][t]);
            float L = 0.0f;
#pragma unroll
            for (int w2 = 0; w2 < 8; w2++)
                L = fmaf(__expf(m_sm[w2][t] - M), l_sm[w2][t], L);
            g_pm[bid * TQ_ + t] = M;
            g_pl[bid * TQ_ + t] = L;
        }
    }
}

__global__ __launch_bounds__(256)
void combine_kernel(float* __restrict__ out)
{
    const int bh = blockIdx.x;          // 0..255
    const int t  = threadIdx.x;
    const int j  = t >> 5;              // query
    const int d4 = (t & 31) << 2;       // column base

    float m[NSPLIT_];
    float M = -INFINITY;
#pragma unroll
    for (int i = 0; i < NSPLIT_; i++) {
        m[i] = g_pm[(bh * NSPLIT_ + i) * TQ_ + j];
        M = fmaxf(M, m[i]);
    }
    float W = 0.0f;
    float ax = 0.f, ay = 0.f, az = 0.f, aw = 0.f;
#pragma unroll
    for (int i = 0; i < NSPLIT_; i++) {
        const float wgt = __expf(m[i] - M);
        W = fmaf(wgt, g_pl[(bh * NSPLIT_ + i) * TQ_ + j], W);
        const float4 oi = *(const float4*)&g_po[((size_t)(bh * NSPLIT_ + i) * TQ_ + j) * D_ + d4];
        ax = fmaf(wgt, oi.x, ax);
        ay = fmaf(wgt, oi.y, ay);
        az = fmaf(wgt, oi.z, az);
        aw = fmaf(wgt, oi.w, aw);
    }
    const float inv = 1.0f / W;
    float4 r = make_float4(ax * inv, ay * inv, az * inv, aw * inv);
    *(float4*)&out[(size_t)bh * (TQ_ * D_) + j * D_ + d4] = r;
}

// diagnostic: pads launch count so ncu (-s 5 -c 1, observed +2 offset)
// lands on attn_split_kernel (profiled slot = our 4th launch)
__global__ void nop_kernel() {}

extern "C" void kernel_launch(void* const* d_in, const int* in_sizes, int n_in,
                              void* d_out, int out_size)
{
    const float* q    = (const float*)d_in[0];
    const float* k    = (const float*)d_in[1];
    const float* v    = (const float*)d_in[2];
    const float* logt = (const float*)d_in[3];
    float* out = (float*)d_out;

    nop_kernel<<<1, 32>>>();
    nop_kernel<<<1, 32>>>();
    nop_kernel<<<1, 32>>>();
    attn_split_kernel<<<NPART_, 256>>>(q, k, v, logt);
    combine_kernel<<<B_ * H_, 256>>>(out);
}